// round 13
// baseline (speedup 1.0000x reference)
#include <cuda_runtime.h>
#include <cstdint>

// Problem dims (fixed by setup_inputs)
#define T_DIM 1024
#define B_DIM 32
#define D_DIM 768
#define N_DIM 64
#define PROJ_C 256          // 4*n : k | v | q | m
#define M_ROWS (T_DIM * B_DIM)

#define LOG2E 1.4426950408889634f

// Scratch: projection results [T, B, 256] fp32 (~33.5 MB) + per-row scalars
__device__ float  g_proj[(size_t)T_DIM * B_DIM * PROJ_C];
__device__ float4 g_scal[(size_t)T_DIM * B_DIM];   // {kk, mm, km, kq}

// ---------------------------------------------------------------------------
__device__ __forceinline__ float ex2f(float x) {
    float y; asm("ex2.approx.ftz.f32 %0, %1;" : "=f"(y) : "f"(x)); return y;
}
__device__ __forceinline__ float rcpf(float x) {
    float y; asm("rcp.approx.ftz.f32 %0, %1;" : "=f"(y) : "f"(x)); return y;
}
__device__ __forceinline__ float tanhf_approx(float x) {
    float y; asm("tanh.approx.f32 %0, %1;" : "=f"(y) : "f"(x)); return y;
}
__device__ __forceinline__ float sigmoidf(float x) {   // high-precision (output path)
    return rcpf(1.0f + ex2f(-x * LOG2E));
}

// ---------------------------------------------------------------------------
// GEMM: proj[r, c] = sum_d x[r, d] * W[c, d]
//   Tile: 128 (M) x 64 (N), BK = 16, 256 threads, 8x4 per-thread microtile
//   (measured at the fp32 FFMA issue roofline — leave as is)
// ---------------------------------------------------------------------------
__global__ void __launch_bounds__(256, 4)
gemm_kernel(const float* __restrict__ A, const float* __restrict__ W) {
    __shared__ float As[16][132];
    __shared__ float Bs[16][68];

    const int bm = blockIdx.x * 128;
    const int bn = blockIdx.y * 64;
    const int t  = threadIdx.x;
    const int tx = t & 15;
    const int ty = t >> 4;

    float acc[8][4];
#pragma unroll
    for (int x = 0; x < 8; ++x)
#pragma unroll
        for (int y = 0; y < 4; ++y) acc[x][y] = 0.0f;

    for (int k0 = 0; k0 < D_DIM; k0 += 16) {
#pragma unroll
        for (int p = 0; p < 2; ++p) {
            int f   = p * 256 + t;
            int row = f >> 2;
            int kq  = (f & 3) * 4;
            float4 v = *(const float4*)(A + (size_t)(bm + row) * D_DIM + k0 + kq);
            As[kq + 0][row] = v.x; As[kq + 1][row] = v.y;
            As[kq + 2][row] = v.z; As[kq + 3][row] = v.w;
        }
        {
            int row = t >> 2;
            int kq  = (t & 3) * 4;
            float4 v = *(const float4*)(W + (size_t)(bn + row) * D_DIM + k0 + kq);
            Bs[kq + 0][row] = v.x; Bs[kq + 1][row] = v.y;
            Bs[kq + 2][row] = v.z; Bs[kq + 3][row] = v.w;
        }
        __syncthreads();

#pragma unroll
        for (int kk = 0; kk < 16; ++kk) {
            float4 a0 = *(const float4*)&As[kk][ty * 8];
            float4 a1 = *(const float4*)&As[kk][ty * 8 + 4];
            float4 bv = *(const float4*)&Bs[kk][tx * 4];
            float a[8]  = {a0.x, a0.y, a0.z, a0.w, a1.x, a1.y, a1.z, a1.w};
            float bb[4] = {bv.x, bv.y, bv.z, bv.w};
#pragma unroll
            for (int x = 0; x < 8; ++x)
#pragma unroll
                for (int y = 0; y < 4; ++y)
                    acc[x][y] = fmaf(a[x], bb[y], acc[x][y]);
        }
        __syncthreads();
    }

#pragma unroll
    for (int x = 0; x < 8; ++x) {
        float4 v = make_float4(acc[x][0], acc[x][1], acc[x][2], acc[x][3]);
        *(float4*)(g_proj + (size_t)(bm + ty * 8 + x) * PROJ_C + bn + tx * 4) = v;
    }
}

// ---------------------------------------------------------------------------
// Normalize k (cols 0:64) and m (cols 192:256) per (t,b) row; also compute
// per-row scalars kk=<kn,kn>, mm=<mn,mn>, km=<kn,mn>, kq=<kn,q>.
// ---------------------------------------------------------------------------
__global__ void norm_kernel() {
    const int w    = (blockIdx.x * blockDim.x + threadIdx.x) >> 5;
    const int lane = threadIdx.x & 31;
    if (w >= M_ROWS) return;
    float* p = g_proj + (size_t)w * PROJ_C;

    float k0 = p[lane],       k1 = p[lane + 32];
    float q0 = p[128 + lane], q1 = p[160 + lane];
    float m0 = p[192 + lane], m1 = p[224 + lane];

    float sk  = fmaf(k0, k0, k1 * k1);
    float sm  = fmaf(m0, m0, m1 * m1);
    float skm = fmaf(k0, m0, k1 * m1);
    float skq = fmaf(k0, q0, k1 * q1);
#pragma unroll
    for (int o = 16; o > 0; o >>= 1) {
        float a = __shfl_xor_sync(0xffffffffu, sk,  o);
        float b = __shfl_xor_sync(0xffffffffu, sm,  o);
        float c = __shfl_xor_sync(0xffffffffu, skm, o);
        float d = __shfl_xor_sync(0xffffffffu, skq, o);
        sk += a; sm += b; skm += c; skq += d;
    }

    float ck = __fdividef(1.0f, sqrtf(sk) + 1e-6f);
    float cm = __fdividef(1.0f, sqrtf(sm) + 1e-6f);
    p[lane]       = k0 * ck;  p[lane + 32] = k1 * ck;
    p[192 + lane] = m0 * cm;  p[224 + lane] = m1 * cm;

    if (lane == 0) {
        float4 sc;
        sc.x = sk  * ck * ck;
        sc.y = sm  * cm * cm;
        sc.z = skm * ck * cm;
        sc.w = skq * ck;
        g_scal[w] = sc;
    }
}

// ---------------------------------------------------------------------------
// Scalar-space RK4 chain, tanh-gate form (verified rel_err 2.4e-7 in R12).
// ---------------------------------------------------------------------------
template<int NS>
__device__ __forceinline__ void rk4_chain(
    int ns_rt, float dt, float h2, float hd6,
    float kk, float mm, float kmh, float vi,
    float p, float rh, float uh, float wv,
    float& A, float& Bc, float& Cc, float& Dc)
{
    A = 1.f; Bc = 0.f; Cc = 1.f; Dc = 0.f;
    float pc = p, rc = rh, uc = uh, wc = wv;
    const int n = (NS > 0) ? NS : ns_rt;
#pragma unroll
    for (int ssi = 0; ssi < n; ++ssi) {
        // hoisted per-substep constants (off critical path)
        const float h2pc = h2 * pc,  dtpc = dt * pc;
        const float h2rc = h2 * rc,  dtrc = dt * rc;
        const float h2uc = h2 * uc,  dtuc = dt * uc;
        const float h2wc = h2 * wc,  dtwc = dt * wc;
        const float h2kk = h2 * kk,  dtkk = dt * kk;
        const float h2km = h2 * kmh, dtkm = dt * kmh;
        const float h2mm = h2 * mm,  dtmm = dt * mm;

        float aSa = 0.f, aSb = 0.f, aGc = 0.f, aGd = 0.f;
        float dSa = 0.f, dSb = 0.f, dGc = 0.f, dGd = 0.f;  // prev-stage derivs
#pragma unroll
        for (int st = 0; st < 4; ++st) {
            float as, bs, cc, dc, p_st, rh_st, uh_st, w_st;
            if (st == 0) {
                as = 1.f; bs = 0.f; cc = 1.f; dc = 0.f;
                p_st = pc; rh_st = rc; uh_st = uc; w_st = wc;
            } else {
                const bool last = (st == 3);
                const float cst  = last ? dt : h2;
                const float cpc  = last ? dtpc : h2pc;
                const float crc  = last ? dtrc : h2rc;
                const float cuc  = last ? dtuc : h2uc;
                const float cwc  = last ? dtwc : h2wc;
                const float ckk  = last ? dtkk : h2kk;
                const float ckm  = last ? dtkm : h2km;
                const float cmm  = last ? dtmm : h2mm;
                as = fmaf(cst, dSa, 1.f);  bs = cst * dSb;
                cc = fmaf(cst, dGc, 1.f);  dc = cst * dGd;
                p_st  = fmaf(dSb, ckk, fmaf(dSa, cpc, pc));
                rh_st = fmaf(dSb, ckm, fmaf(dSa, crc, rc));
                uh_st = fmaf(dGd, ckm, fmaf(dGc, cuc, uc));
                w_st  = fmaf(dGd, cmm, fmaf(dGc, cwc, wc));
            }
            // gates via tanh: an = 1 - sigmoid(u) = 0.5 - 0.5*tanh(u/2)
            float Tu = tanhf_approx(uh_st);
            float Tr = tanhf_approx(rh_st);
            float dSs = vi - p_st;
            float dGs = dSs - w_st;
            float has = 0.5f * as, hbs = 0.5f * bs;
            float hcc = 0.5f * cc, hdc = 0.5f * dc;
            dSa = fmaf(Tu, has, -has);          // -an*as
            dSb = fmaf(Tu, hbs, dSs - hbs);     // dSs - an*bs
            dGc = fmaf(Tr, hcc, -hcc);
            dGd = fmaf(Tr, hdc, dGs - hdc);
            float wgt = (st == 1 || st == 2) ? 2.0f : 1.0f;
            aSa = fmaf(wgt, dSa, aSa);
            aSb = fmaf(wgt, dSb, aSb);
            aGc = fmaf(wgt, dGc, aGc);
            aGd = fmaf(wgt, dGd, aGd);
        }
        float a_s = fmaf(hd6, aSa, 1.0f), b_s = hd6 * aSb;
        float c_g = fmaf(hd6, aGc, 1.0f), d_g = hd6 * aGd;
        A  = a_s * A;  Bc = fmaf(a_s, Bc, b_s);
        Cc = c_g * Cc; Dc = fmaf(c_g, Dc, d_g);
        pc = fmaf(b_s, kk,  a_s * pc);
        rc = fmaf(b_s, kmh, a_s * rc);
        uc = fmaf(d_g, kmh, c_g * uc);
        wc = fmaf(d_g, mm,  c_g * wc);
    }
}

// ---------------------------------------------------------------------------
// 3-warp specialized scan. Block = 96 threads, owns 8 rows of one batch.
//   warp 0 (V0): owns s, kc  — 6 dots (s,kc x kn,mn,qn), s update, loads kn/mn/qn
//   warp 1 (V1): owns g, mc  — 4 dots (g,mc x kn,mn),   g update, loads kn/mn
//   warp 2 (CH): serial RK4 scalar chain
// Vector warps each sit under the chain's ~600-cyc window (R12's single
// vector warp at ~800-900 cyc was the binder). Double-buffered smem, one
// __syncthreads per timestep: at iter t, read slot (t+1)&1, write slot t&1.
// ---------------------------------------------------------------------------
template<int NS>
__device__ __forceinline__ void scan_impl(
    const float* __restrict__ S0, const float* __restrict__ G0,
    float* __restrict__ out, int ns_rt,
    float rd[2][8][12], float4 abcd[2][8])
{
    const int b    = (int)blockIdx.x >> 3;
    const int rg   = (int)blockIdx.x & 7;
    const int wid  = threadIdx.x >> 5;        // 0,1 = vector, 2 = chain
    const int lane = threadIdx.x & 31;
    const int rl   = lane >> 2;               // row in group (0..7)
    const int cb   = lane & 3;                // column block (0..3)
    const int i    = rg * 8 + rl;             // global row 0..63
    const int cofs = cb * 16;

    const float dt  = __fdividef(1.0f, (float)((NS > 0) ? NS : ns_rt));
    const float h2  = 0.5f * dt;
    const float hd6 = dt * (1.0f / 6.0f);

    const size_t sbase = ((size_t)b * N_DIM + i) * N_DIM + cofs;

    if (wid == 0) {
        // ============ V0: s-side (s, kc; dots with kn, mn, qn) ============
        float s[16], kc[16], kn[16], mn[16], qn[16];
#pragma unroll
        for (int j = 0; j < 4; ++j) {
            float4 a = *(const float4*)(S0 + sbase + j * 4);
            s[j*4+0]=a.x; s[j*4+1]=a.y; s[j*4+2]=a.z; s[j*4+3]=a.w;
        }
        {
            const float* pp = g_proj + ((size_t)b << 8);
#pragma unroll
            for (int j = 0; j < 4; ++j) {
                float4 a = *(const float4*)(pp + cofs + j * 4);
                kn[j*4+0]=a.x; kn[j*4+1]=a.y; kn[j*4+2]=a.z; kn[j*4+3]=a.w;
                float4 c = *(const float4*)(pp + 192 + cofs + j * 4);
                mn[j*4+0]=c.x; mn[j*4+1]=c.y; mn[j*4+2]=c.z; mn[j*4+3]=c.w;
                float4 d = *(const float4*)(pp + 128 + cofs + j * 4);
                qn[j*4+0]=d.x; qn[j*4+1]=d.y; qn[j*4+2]=d.z; qn[j*4+3]=d.w;
            }
#pragma unroll
            for (int j = 0; j < 16; ++j) kc[j] = kn[j];
        }
        // Prologue: s dots with t=0 vectors -> rd[1][..][0..2]; k-dots slots 0.
        {
            float d0=0.f,d1=0.f,d2=0.f;
#pragma unroll
            for (int j = 0; j < 16; ++j) {
                d0 = fmaf(s[j], kn[j], d0);
                d1 = fmaf(s[j], mn[j], d1);
                d2 = fmaf(s[j], qn[j], d2);
            }
#pragma unroll
            for (int o = 1; o <= 2; o <<= 1) {
                d0 += __shfl_xor_sync(0xffffffffu, d0, o);
                d1 += __shfl_xor_sync(0xffffffffu, d1, o);
                d2 += __shfl_xor_sync(0xffffffffu, d2, o);
            }
            if (cb == 0) {
                float* r = rd[1][rl];
                r[0]=d0; r[1]=d1; r[2]=d2;
                r[5]=0.f; r[6]=0.f; r[7]=0.f;
                abcd[1][rl] = make_float4(1.f, 0.f, 1.f, 0.f);
            }
        }
        __syncthreads();   // prologue published

        for (int t = 0; t < T_DIM; ++t) {
            float4 ab = abcd[(t + 1) & 1][rl];      // A,B of step t-1
            float nk[16], nmn[16], nq[16];
            {
                const int tn = (t + 1 < T_DIM) ? t + 1 : t;
                const float* np = g_proj + ((size_t)(tn * B_DIM + b) << 8);
#pragma unroll
                for (int j = 0; j < 4; ++j) {
                    float4 a = *(const float4*)(np + cofs + j * 4);
                    nk[j*4+0]=a.x; nk[j*4+1]=a.y; nk[j*4+2]=a.z; nk[j*4+3]=a.w;
                    float4 c = *(const float4*)(np + 192 + cofs + j * 4);
                    nmn[j*4+0]=c.x; nmn[j*4+1]=c.y; nmn[j*4+2]=c.z; nmn[j*4+3]=c.w;
                    float4 d = *(const float4*)(np + 128 + cofs + j * 4);
                    nq[j*4+0]=d.x; nq[j*4+1]=d.y; nq[j*4+2]=d.z; nq[j*4+3]=d.w;
                }
            }
            // update s with A,B(t-1); shift kc <- kn
            float skp=0.f, smp=0.f, sqp=0.f, kkx=0.f, kmx=0.f, kqx=0.f;
#pragma unroll
            for (int j = 0; j < 16; ++j) {
                s[j]  = fmaf(ab.x, s[j], ab.y * kc[j]);
                kc[j] = kn[j];
                kn[j] = nk[j];
                mn[j] = nmn[j];
                qn[j] = nq[j];
                skp = fmaf(s[j],  kn[j], skp);
                smp = fmaf(s[j],  mn[j], smp);
                sqp = fmaf(s[j],  qn[j], sqp);
                kkx = fmaf(kc[j], kn[j], kkx);
                kmx = fmaf(kc[j], mn[j], kmx);
                kqx = fmaf(kc[j], qn[j], kqx);
            }
#pragma unroll
            for (int o = 1; o <= 2; o <<= 1) {
                skp += __shfl_xor_sync(0xffffffffu, skp, o);
                smp += __shfl_xor_sync(0xffffffffu, smp, o);
                sqp += __shfl_xor_sync(0xffffffffu, sqp, o);
                kkx += __shfl_xor_sync(0xffffffffu, kkx, o);
                kmx += __shfl_xor_sync(0xffffffffu, kmx, o);
                kqx += __shfl_xor_sync(0xffffffffu, kqx, o);
            }
            if (cb == 0) {
                float* r = rd[t & 1][rl];
                r[0]=skp; r[1]=smp; r[2]=sqp;
                r[5]=kkx; r[6]=kmx; r[7]=kqx;
            }
            __syncthreads();
        }

        // Final update with A..D(T-1) and S writeback
        {
            float4 ab = abcd[(T_DIM - 1) & 1][rl];
#pragma unroll
            for (int j = 0; j < 16; ++j)
                s[j] = fmaf(ab.x, s[j], ab.y * kc[j]);
            float* Sout = out + (size_t)T_DIM * B_DIM * N_DIM;
#pragma unroll
            for (int j = 0; j < 4; ++j)
                *(float4*)(Sout + sbase + j * 4) =
                    make_float4(s[j*4], s[j*4+1], s[j*4+2], s[j*4+3]);
        }
    } else if (wid == 1) {
        // ============ V1: g-side (g, mc; dots with kn, mn) ============
        float g[16], mc[16], kn[16], mn[16];
#pragma unroll
        for (int j = 0; j < 4; ++j) {
            float4 c = *(const float4*)(G0 + sbase + j * 4);
            g[j*4+0]=c.x; g[j*4+1]=c.y; g[j*4+2]=c.z; g[j*4+3]=c.w;
        }
        {
            const float* pp = g_proj + ((size_t)b << 8);
#pragma unroll
            for (int j = 0; j < 4; ++j) {
                float4 a = *(const float4*)(pp + cofs + j * 4);
                kn[j*4+0]=a.x; kn[j*4+1]=a.y; kn[j*4+2]=a.z; kn[j*4+3]=a.w;
                float4 c = *(const float4*)(pp + 192 + cofs + j * 4);
                mn[j*4+0]=c.x; mn[j*4+1]=c.y; mn[j*4+2]=c.z; mn[j*4+3]=c.w;
            }
#pragma unroll
            for (int j = 0; j < 16; ++j) mc[j] = mn[j];
        }
        // Prologue: g dots -> rd[1][..][3..4]; m-dots slots 0.
        {
            float d3=0.f,d4=0.f;
#pragma unroll
            for (int j = 0; j < 16; ++j) {
                d3 = fmaf(g[j], kn[j], d3);
                d4 = fmaf(g[j], mn[j], d4);
            }
#pragma unroll
            for (int o = 1; o <= 2; o <<= 1) {
                d3 += __shfl_xor_sync(0xffffffffu, d3, o);
                d4 += __shfl_xor_sync(0xffffffffu, d4, o);
            }
            if (cb == 0) {
                float* r = rd[1][rl];
                r[3]=d3; r[4]=d4;
                r[8]=0.f; r[9]=0.f;
            }
        }
        __syncthreads();   // prologue published

        for (int t = 0; t < T_DIM; ++t) {
            float4 ab = abcd[(t + 1) & 1][rl];      // C,D of step t-1
            float nk[16], nmn[16];
            {
                const int tn = (t + 1 < T_DIM) ? t + 1 : t;
                const float* np = g_proj + ((size_t)(tn * B_DIM + b) << 8);
#pragma unroll
                for (int j = 0; j < 4; ++j) {
                    float4 a = *(const float4*)(np + cofs + j * 4);
                    nk[j*4+0]=a.x; nk[j*4+1]=a.y; nk[j*4+2]=a.z; nk[j*4+3]=a.w;
                    float4 c = *(const float4*)(np + 192 + cofs + j * 4);
                    nmn[j*4+0]=c.x; nmn[j*4+1]=c.y; nmn[j*4+2]=c.z; nmn[j*4+3]=c.w;
                }
            }
            float gkp=0.f, gmp=0.f, mkx=0.f, mmx=0.f;
#pragma unroll
            for (int j = 0; j < 16; ++j) {
                g[j]  = fmaf(ab.z, g[j], ab.w * mc[j]);
                mc[j] = mn[j];
                kn[j] = nk[j];
                mn[j] = nmn[j];
                gkp = fmaf(g[j],  kn[j], gkp);
                gmp = fmaf(g[j],  mn[j], gmp);
                mkx = fmaf(mc[j], kn[j], mkx);
                mmx = fmaf(mc[j], mn[j], mmx);
            }
#pragma unroll
            for (int o = 1; o <= 2; o <<= 1) {
                gkp += __shfl_xor_sync(0xffffffffu, gkp, o);
                gmp += __shfl_xor_sync(0xffffffffu, gmp, o);
                mkx += __shfl_xor_sync(0xffffffffu, mkx, o);
                mmx += __shfl_xor_sync(0xffffffffu, mmx, o);
            }
            if (cb == 0) {
                float* r = rd[t & 1][rl];
                r[3]=gkp; r[4]=gmp;
                r[8]=mkx; r[9]=mmx;
            }
            __syncthreads();
        }

        // Final update + G writeback
        {
            float4 ab = abcd[(T_DIM - 1) & 1][rl];
#pragma unroll
            for (int j = 0; j < 16; ++j)
                g[j] = fmaf(ab.z, g[j], ab.w * mc[j]);
            float* Gout = out + (size_t)T_DIM * B_DIM * N_DIM
                              + (size_t)B_DIM * N_DIM * N_DIM;
#pragma unroll
            for (int j = 0; j < 4; ++j)
                *(float4*)(Gout + sbase + j * 4) =
                    make_float4(g[j*4], g[j*4+1], g[j*4+2], g[j*4+3]);
        }
    } else {
        // ================= CHAIN warp =================
        float Ap = 1.f, Bp = 0.f, Cp = 1.f, Dp = 0.f;   // A..D(t-1)
        float vi_c = g_proj[((size_t)b << 8) + 64 + i]; // v_0[i]
        float4 sc_c = g_scal[b];
        __syncthreads();   // prologue published

        for (int t = 0; t < T_DIM; ++t) {
            const int tn = (t + 1 < T_DIM) ? t + 1 : t;
            float  vi_n = g_proj[((size_t)(tn * B_DIM + b) << 8) + 64 + i];
            float4 sc_n = g_scal[tn * B_DIM + b];

            // combine raw dots (slot (t+1)&1, written at t-1) with A..D(t-1)
            const float* r = rd[(t + 1) & 1][rl];
            float p  = fmaf(Bp, r[5], Ap * r[0]);
            float rh = 0.5f * fmaf(Bp, r[6], Ap * r[1]);   // <s,m>/2
            float zz = fmaf(Bp, r[7], Ap * r[2]);
            float uh = 0.5f * fmaf(Dp, r[8], Cp * r[3]);   // <g,k>/2
            float wv = fmaf(Dp, r[9], Cp * r[4]);

            const float kk  = sc_c.x, mm = sc_c.y, kq = sc_c.w;
            const float kmh = 0.5f * sc_c.z;

            float A, Bc, Cc, Dc;
            rk4_chain<NS>(ns_rt, dt, h2, hd6, kk, mm, kmh, vi_c,
                          p, rh, uh, wv, A, Bc, Cc, Dc);

            // output: z = <s_end, q_t> = A*zz + B*kq
            float z = fmaf(Bc, kq, A * zz);
            if (cb == 0) {
                out[((size_t)t * B_DIM + b) * N_DIM + i] = z * z * sigmoidf(z);
                abcd[t & 1][rl] = make_float4(A, Bc, Cc, Dc);
            }
            Ap = A; Bp = Bc; Cp = Cc; Dp = Dc;
            vi_c = vi_n; sc_c = sc_n;
            __syncthreads();   // publish abcd[t&1] / rd[t&1]
        }
    }
}

__global__ void __launch_bounds__(96)
scan_kernel(const float* __restrict__ S0,
            const float* __restrict__ G0,
            const int*   __restrict__ ns_ptr,
            float* __restrict__ out) {
    __shared__ float  rd[2][8][12];
    __shared__ float4 abcd[2][8];

    const int ns = ns_ptr ? *ns_ptr : 4;
    if (ns == 4) {
        scan_impl<4>(S0, G0, out, 4, rd, abcd);
    } else {
        scan_impl<0>(S0, G0, out, ns, rd, abcd);
    }
}

// ---------------------------------------------------------------------------
extern "C" void kernel_launch(void* const* d_in, const int* in_sizes, int n_in,
                              void* d_out, int out_size) {
    const float* x  = (const float*)d_in[0];   // [T, B, 768]
    const float* S0 = (const float*)d_in[1];   // [B, 64, 64]
    const float* G0 = (const float*)d_in[2];   // [B, 64, 64]
    const float* W  = (const float*)d_in[3];   // [256, 768]
    const int*   ns = (n_in > 4) ? (const int*)d_in[4] : nullptr;
    float* out = (float*)d_out;

    dim3 ggrid(M_ROWS / 128, PROJ_C / 64);
    gemm_kernel<<<ggrid, 256>>>(x, W);

    norm_kernel<<<(M_ROWS * 32) / 256, 256>>>();

    // 256 blocks x 96 threads: V0 (s-side), V1 (g-side), chain
    scan_kernel<<<256, 96>>>(S0, G0, ns, out);
}

// round 15
// speedup vs baseline: 1.0473x; 1.0473x over previous
#include <cuda_runtime.h>
#include <cstdint>

// Problem dims (fixed by setup_inputs)
#define T_DIM 1024
#define B_DIM 32
#define D_DIM 768
#define N_DIM 64
#define PROJ_C 256          // 4*n : k | v | q | m
#define M_ROWS (T_DIM * B_DIM)

#define LOG2E 1.4426950408889634f

// Scratch: projection results [T, B, 256] fp32 (~33.5 MB) + per-row scalars
__device__ float  g_proj[(size_t)T_DIM * B_DIM * PROJ_C];
__device__ float4 g_scal[(size_t)T_DIM * B_DIM];   // {kk, mm, km, kq}

// ---------------------------------------------------------------------------
__device__ __forceinline__ float ex2f(float x) {
    float y; asm("ex2.approx.ftz.f32 %0, %1;" : "=f"(y) : "f"(x)); return y;
}
__device__ __forceinline__ float rcpf(float x) {
    float y; asm("rcp.approx.ftz.f32 %0, %1;" : "=f"(y) : "f"(x)); return y;
}
__device__ __forceinline__ float tanhf_approx(float x) {
    float y; asm("tanh.approx.f32 %0, %1;" : "=f"(y) : "f"(x)); return y;
}
__device__ __forceinline__ float sigmoidf(float x) {   // high-precision (output path)
    return rcpf(1.0f + ex2f(-x * LOG2E));
}

// ---------------------------------------------------------------------------
// GEMM: proj[r, c] = sum_d x[r, d] * W[c, d]
// 128x128 tile, BK=16, 256 threads, 8x8 microtile (N split 4+4 for
// conflict-free LDS). Register-prefetch pipeline: LDG of tile k+1 issues
// before the compute of tile k, hiding global latency under 1024 FMA/thread.
// Accumulation order over k identical to the previous kernel (bitwise-same).
// ---------------------------------------------------------------------------
__global__ void __launch_bounds__(256, 2)
gemm_kernel(const float* __restrict__ A, const float* __restrict__ W) {
    __shared__ float As[16][132];
    __shared__ float Bs[16][132];

    const int bm = blockIdx.x * 128;
    const int bn = blockIdx.y * 128;
    const int t  = threadIdx.x;
    const int tx = t & 15;      // N dir: 2 x (16 x 4) = 128
    const int ty = t >> 4;      // M dir: 16 x 8 = 128

    const int lrow = t >> 2;        // 0..63
    const int lkq  = (t & 3) * 4;   // 0,4,8,12

    float acc[8][8];
#pragma unroll
    for (int x = 0; x < 8; ++x)
#pragma unroll
        for (int y = 0; y < 8; ++y) acc[x][y] = 0.0f;

    // prologue: load tile 0 into registers
    float4 pa[2], pb[2];
#pragma unroll
    for (int p = 0; p < 2; ++p) {
        pa[p] = *(const float4*)(A + (size_t)(bm + p * 64 + lrow) * D_DIM + lkq);
        pb[p] = *(const float4*)(W + (size_t)(bn + p * 64 + lrow) * D_DIM + lkq);
    }

    for (int k0 = 0; k0 < D_DIM; k0 += 16) {
        // store staged tile to smem (transposed)
#pragma unroll
        for (int p = 0; p < 2; ++p) {
            int r = p * 64 + lrow;
            As[lkq + 0][r] = pa[p].x; As[lkq + 1][r] = pa[p].y;
            As[lkq + 2][r] = pa[p].z; As[lkq + 3][r] = pa[p].w;
            Bs[lkq + 0][r] = pb[p].x; Bs[lkq + 1][r] = pb[p].y;
            Bs[lkq + 2][r] = pb[p].z; Bs[lkq + 3][r] = pb[p].w;
        }
        __syncthreads();

        // prefetch next tile (resolves under the compute below)
        if (k0 + 16 < D_DIM) {
#pragma unroll
            for (int p = 0; p < 2; ++p) {
                pa[p] = *(const float4*)(A + (size_t)(bm + p * 64 + lrow) * D_DIM + k0 + 16 + lkq);
                pb[p] = *(const float4*)(W + (size_t)(bn + p * 64 + lrow) * D_DIM + k0 + 16 + lkq);
            }
        }

#pragma unroll
        for (int kk = 0; kk < 16; ++kk) {
            float4 a0 = *(const float4*)&As[kk][ty * 8];
            float4 a1 = *(const float4*)&As[kk][ty * 8 + 4];
            float4 b0 = *(const float4*)&Bs[kk][tx * 4];
            float4 b1 = *(const float4*)&Bs[kk][64 + tx * 4];
            float a[8]  = {a0.x, a0.y, a0.z, a0.w, a1.x, a1.y, a1.z, a1.w};
            float bb[8] = {b0.x, b0.y, b0.z, b0.w, b1.x, b1.y, b1.z, b1.w};
#pragma unroll
            for (int x = 0; x < 8; ++x)
#pragma unroll
                for (int y = 0; y < 8; ++y)
                    acc[x][y] = fmaf(a[x], bb[y], acc[x][y]);
        }
        __syncthreads();
    }

    // store: columns bn + tx*4 (+0) and bn + 64 + tx*4
#pragma unroll
    for (int x = 0; x < 8; ++x) {
        float* dst = g_proj + (size_t)(bm + ty * 8 + x) * PROJ_C + bn;
        *(float4*)(dst + tx * 4)      = make_float4(acc[x][0], acc[x][1], acc[x][2], acc[x][3]);
        *(float4*)(dst + 64 + tx * 4) = make_float4(acc[x][4], acc[x][5], acc[x][6], acc[x][7]);
    }
}

// ---------------------------------------------------------------------------
// Normalize k (cols 0:64) and m (cols 192:256) per (t,b) row; also compute
// per-row scalars kk=<kn,kn>, mm=<mn,mn>, km=<kn,mn>, kq=<kn,q>.
// ---------------------------------------------------------------------------
__global__ void norm_kernel() {
    const int w    = (blockIdx.x * blockDim.x + threadIdx.x) >> 5;
    const int lane = threadIdx.x & 31;
    if (w >= M_ROWS) return;
    float* p = g_proj + (size_t)w * PROJ_C;

    float k0 = p[lane],       k1 = p[lane + 32];
    float q0 = p[128 + lane], q1 = p[160 + lane];
    float m0 = p[192 + lane], m1 = p[224 + lane];

    float sk  = fmaf(k0, k0, k1 * k1);
    float sm  = fmaf(m0, m0, m1 * m1);
    float skm = fmaf(k0, m0, k1 * m1);
    float skq = fmaf(k0, q0, k1 * q1);
#pragma unroll
    for (int o = 16; o > 0; o >>= 1) {
        float a = __shfl_xor_sync(0xffffffffu, sk,  o);
        float b = __shfl_xor_sync(0xffffffffu, sm,  o);
        float c = __shfl_xor_sync(0xffffffffu, skm, o);
        float d = __shfl_xor_sync(0xffffffffu, skq, o);
        sk += a; sm += b; skm += c; skq += d;
    }

    float ck = __fdividef(1.0f, sqrtf(sk) + 1e-6f);
    float cm = __fdividef(1.0f, sqrtf(sm) + 1e-6f);
    p[lane]       = k0 * ck;  p[lane + 32] = k1 * ck;
    p[192 + lane] = m0 * cm;  p[224 + lane] = m1 * cm;

    if (lane == 0) {
        float4 sc;
        sc.x = sk  * ck * ck;
        sc.y = sm  * cm * cm;
        sc.z = skm * ck * cm;
        sc.w = skq * ck;
        g_scal[w] = sc;
    }
}

// ---------------------------------------------------------------------------
// Scalar-space RK4 chain, tanh-gate form (verified rel_err 2.4e-7 in R12).
// ---------------------------------------------------------------------------
template<int NS>
__device__ __forceinline__ void rk4_chain(
    int ns_rt, float dt, float h2, float hd6,
    float kk, float mm, float kmh, float vi,
    float p, float rh, float uh, float wv,
    float& A, float& Bc, float& Cc, float& Dc)
{
    A = 1.f; Bc = 0.f; Cc = 1.f; Dc = 0.f;
    float pc = p, rc = rh, uc = uh, wc = wv;
    const int n = (NS > 0) ? NS : ns_rt;
#pragma unroll
    for (int ssi = 0; ssi < n; ++ssi) {
        // hoisted per-substep constants (off critical path)
        const float h2pc = h2 * pc,  dtpc = dt * pc;
        const float h2rc = h2 * rc,  dtrc = dt * rc;
        const float h2uc = h2 * uc,  dtuc = dt * uc;
        const float h2wc = h2 * wc,  dtwc = dt * wc;
        const float h2kk = h2 * kk,  dtkk = dt * kk;
        const float h2km = h2 * kmh, dtkm = dt * kmh;
        const float h2mm = h2 * mm,  dtmm = dt * mm;

        float aSa = 0.f, aSb = 0.f, aGc = 0.f, aGd = 0.f;
        float dSa = 0.f, dSb = 0.f, dGc = 0.f, dGd = 0.f;  // prev-stage derivs
#pragma unroll
        for (int st = 0; st < 4; ++st) {
            float as, bs, cc, dc, p_st, rh_st, uh_st, w_st;
            if (st == 0) {
                as = 1.f; bs = 0.f; cc = 1.f; dc = 0.f;
                p_st = pc; rh_st = rc; uh_st = uc; w_st = wc;
            } else {
                const bool last = (st == 3);
                const float cst  = last ? dt : h2;
                const float cpc  = last ? dtpc : h2pc;
                const float crc  = last ? dtrc : h2rc;
                const float cuc  = last ? dtuc : h2uc;
                const float cwc  = last ? dtwc : h2wc;
                const float ckk  = last ? dtkk : h2kk;
                const float ckm  = last ? dtkm : h2km;
                const float cmm  = last ? dtmm : h2mm;
                as = fmaf(cst, dSa, 1.f);  bs = cst * dSb;
                cc = fmaf(cst, dGc, 1.f);  dc = cst * dGd;
                p_st  = fmaf(dSb, ckk, fmaf(dSa, cpc, pc));
                rh_st = fmaf(dSb, ckm, fmaf(dSa, crc, rc));
                uh_st = fmaf(dGd, ckm, fmaf(dGc, cuc, uc));
                w_st  = fmaf(dGd, cmm, fmaf(dGc, cwc, wc));
            }
            // gates via tanh: an = 1 - sigmoid(u) = 0.5 - 0.5*tanh(u/2)
            float Tu = tanhf_approx(uh_st);
            float Tr = tanhf_approx(rh_st);
            float dSs = vi - p_st;
            float dGs = dSs - w_st;
            float has = 0.5f * as, hbs = 0.5f * bs;
            float hcc = 0.5f * cc, hdc = 0.5f * dc;
            dSa = fmaf(Tu, has, -has);          // -an*as
            dSb = fmaf(Tu, hbs, dSs - hbs);     // dSs - an*bs
            dGc = fmaf(Tr, hcc, -hcc);
            dGd = fmaf(Tr, hdc, dGs - hdc);
            float wgt = (st == 1 || st == 2) ? 2.0f : 1.0f;
            aSa = fmaf(wgt, dSa, aSa);
            aSb = fmaf(wgt, dSb, aSb);
            aGc = fmaf(wgt, dGc, aGc);
            aGd = fmaf(wgt, dGd, aGd);
        }
        float a_s = fmaf(hd6, aSa, 1.0f), b_s = hd6 * aSb;
        float c_g = fmaf(hd6, aGc, 1.0f), d_g = hd6 * aGd;
        A  = a_s * A;  Bc = fmaf(a_s, Bc, b_s);
        Cc = c_g * Cc; Dc = fmaf(c_g, Dc, d_g);
        pc = fmaf(b_s, kk,  a_s * pc);
        rc = fmaf(b_s, kmh, a_s * rc);
        uc = fmaf(d_g, kmh, c_g * uc);
        wc = fmaf(d_g, mm,  c_g * wc);
    }
}

// ---------------------------------------------------------------------------
// Warp-specialized scan (R12 structure — measured 999.9 us total).
// Block = 2 warps, 8 rows. Warp 0 = VECTOR (state + raw dots), warp 1 = CHAIN.
// Double-buffered smem: at iteration t both warps READ slot (t+1)&1 and WRITE
// slot t&1 — single producer/consumer per buffer, so ONE __syncthreads at the
// end of each iteration is race-free.
// ---------------------------------------------------------------------------
template<int NS>
__device__ __forceinline__ void scan_impl(
    const float* __restrict__ S0, const float* __restrict__ G0,
    float* __restrict__ out, int ns_rt,
    float rd[2][8][12], float4 abcd[2][8])
{
    const int b    = (int)blockIdx.x >> 3;
    const int rg   = (int)blockIdx.x & 7;
    const int wid  = threadIdx.x >> 5;        // 0 = vector, 1 = chain
    const int lane = threadIdx.x & 31;
    const int rl   = lane >> 2;               // row in group (0..7)
    const int cb   = lane & 3;                // column block (0..3)
    const int i    = rg * 8 + rl;             // global row 0..63
    const int cofs = cb * 16;

    const float dt  = __fdividef(1.0f, (float)((NS > 0) ? NS : ns_rt));
    const float h2  = 0.5f * dt;
    const float hd6 = dt * (1.0f / 6.0f);

    const size_t sbase = ((size_t)b * N_DIM + i) * N_DIM + cofs;

    if (wid == 0) {
        // ================= VECTOR warp =================
        float s[16], g[16], kc[16], mc[16], kn[16], mn[16], qn[16];
#pragma unroll
        for (int j = 0; j < 4; ++j) {
            float4 a = *(const float4*)(S0 + sbase + j * 4);
            s[j*4+0]=a.x; s[j*4+1]=a.y; s[j*4+2]=a.z; s[j*4+3]=a.w;
            float4 c = *(const float4*)(G0 + sbase + j * 4);
            g[j*4+0]=c.x; g[j*4+1]=c.y; g[j*4+2]=c.z; g[j*4+3]=c.w;
        }
        {   // t = 0 vectors into the "next" slots
            const float* pp = g_proj + ((size_t)b << 8);
#pragma unroll
            for (int j = 0; j < 4; ++j) {
                float4 a = *(const float4*)(pp + cofs + j * 4);
                kn[j*4+0]=a.x; kn[j*4+1]=a.y; kn[j*4+2]=a.z; kn[j*4+3]=a.w;
                float4 c = *(const float4*)(pp + 192 + cofs + j * 4);
                mn[j*4+0]=c.x; mn[j*4+1]=c.y; mn[j*4+2]=c.z; mn[j*4+3]=c.w;
                float4 d = *(const float4*)(pp + 128 + cofs + j * 4);
                qn[j*4+0]=d.x; qn[j*4+1]=d.y; qn[j*4+2]=d.z; qn[j*4+3]=d.w;
            }
#pragma unroll
            for (int j = 0; j < 16; ++j) { kc[j] = kn[j]; mc[j] = mn[j]; }
        }
        // Prologue: dots of initial state with t=0 vectors -> rd[1];
        // abcd[1] = identity so iter-0 update is a no-op.
        {
            float d0=0.f,d1=0.f,d2=0.f,d3=0.f,d4=0.f;
#pragma unroll
            for (int j = 0; j < 16; ++j) {
                d0 = fmaf(s[j], kn[j], d0);
                d1 = fmaf(s[j], mn[j], d1);
                d2 = fmaf(s[j], qn[j], d2);
                d3 = fmaf(g[j], kn[j], d3);
                d4 = fmaf(g[j], mn[j], d4);
            }
#pragma unroll
            for (int o = 1; o <= 2; o <<= 1) {
                d0 += __shfl_xor_sync(0xffffffffu, d0, o);
                d1 += __shfl_xor_sync(0xffffffffu, d1, o);
                d2 += __shfl_xor_sync(0xffffffffu, d2, o);
                d3 += __shfl_xor_sync(0xffffffffu, d3, o);
                d4 += __shfl_xor_sync(0xffffffffu, d4, o);
            }
            if (cb == 0) {
                float* r = rd[1][rl];
                r[0]=d0; r[1]=d1; r[2]=d2; r[3]=d3; r[4]=d4;
                r[5]=0.f; r[6]=0.f; r[7]=0.f; r[8]=0.f; r[9]=0.f;
                abcd[1][rl] = make_float4(1.f, 0.f, 1.f, 0.f);
            }
        }
        __syncthreads();   // prologue published

        for (int t = 0; t < T_DIM; ++t) {
            // update with A..D(t-1) from slot (t+1)&1
            float4 ab = abcd[(t + 1) & 1][rl];
#pragma unroll
            for (int j = 0; j < 16; ++j) {
                s[j] = fmaf(ab.x, s[j], ab.y * kc[j]);
                g[j] = fmaf(ab.z, g[j], ab.w * mc[j]);
                kc[j] = kn[j];
                mc[j] = mn[j];
            }
            // prefetch t+1 vectors
            {
                const int tn = (t + 1 < T_DIM) ? t + 1 : t;
                const float* np = g_proj + ((size_t)(tn * B_DIM + b) << 8);
#pragma unroll
                for (int j = 0; j < 4; ++j) {
                    float4 a = *(const float4*)(np + cofs + j * 4);
                    kn[j*4+0]=a.x; kn[j*4+1]=a.y; kn[j*4+2]=a.z; kn[j*4+3]=a.w;
                    float4 c = *(const float4*)(np + 192 + cofs + j * 4);
                    mn[j*4+0]=c.x; mn[j*4+1]=c.y; mn[j*4+2]=c.z; mn[j*4+3]=c.w;
                    float4 d = *(const float4*)(np + 128 + cofs + j * 4);
                    qn[j*4+0]=d.x; qn[j*4+1]=d.y; qn[j*4+2]=d.z; qn[j*4+3]=d.w;
                }
            }
            // 10 raw dots: {s,g,kc,mc} x {kn,mn,qn}
            float skp=0.f, smp=0.f, sqp=0.f, gkp=0.f, gmp=0.f;
            float kkx=0.f, kmx=0.f, kqx=0.f, mkx=0.f, mmx=0.f;
#pragma unroll
            for (int j = 0; j < 16; ++j) {
                skp = fmaf(s[j],  kn[j], skp);
                smp = fmaf(s[j],  mn[j], smp);
                sqp = fmaf(s[j],  qn[j], sqp);
                gkp = fmaf(g[j],  kn[j], gkp);
                gmp = fmaf(g[j],  mn[j], gmp);
                kkx = fmaf(kc[j], kn[j], kkx);
                kmx = fmaf(kc[j], mn[j], kmx);
                kqx = fmaf(kc[j], qn[j], kqx);
                mkx = fmaf(mc[j], kn[j], mkx);
                mmx = fmaf(mc[j], mn[j], mmx);
            }
#pragma unroll
            for (int o = 1; o <= 2; o <<= 1) {
                skp += __shfl_xor_sync(0xffffffffu, skp, o);
                smp += __shfl_xor_sync(0xffffffffu, smp, o);
                sqp += __shfl_xor_sync(0xffffffffu, sqp, o);
                gkp += __shfl_xor_sync(0xffffffffu, gkp, o);
                gmp += __shfl_xor_sync(0xffffffffu, gmp, o);
                kkx += __shfl_xor_sync(0xffffffffu, kkx, o);
                kmx += __shfl_xor_sync(0xffffffffu, kmx, o);
                kqx += __shfl_xor_sync(0xffffffffu, kqx, o);
                mkx += __shfl_xor_sync(0xffffffffu, mkx, o);
                mmx += __shfl_xor_sync(0xffffffffu, mmx, o);
            }
            if (cb == 0) {
                float* r = rd[t & 1][rl];
                r[0]=skp; r[1]=smp; r[2]=sqp; r[3]=gkp; r[4]=gmp;
                r[5]=kkx; r[6]=kmx; r[7]=kqx; r[8]=mkx; r[9]=mmx;
            }
            __syncthreads();   // publish rd[t&1] / abcd[t&1]
        }

        // Final update with A..D(T-1) and state writeback
        {
            float4 ab = abcd[(T_DIM - 1) & 1][rl];
#pragma unroll
            for (int j = 0; j < 16; ++j) {
                s[j] = fmaf(ab.x, s[j], ab.y * kc[j]);
                g[j] = fmaf(ab.z, g[j], ab.w * mc[j]);
            }
            float* Sout = out + (size_t)T_DIM * B_DIM * N_DIM;
            float* Gout = Sout + (size_t)B_DIM * N_DIM * N_DIM;
#pragma unroll
            for (int j = 0; j < 4; ++j) {
                *(float4*)(Sout + sbase + j * 4) =
                    make_float4(s[j*4], s[j*4+1], s[j*4+2], s[j*4+3]);
                *(float4*)(Gout + sbase + j * 4) =
                    make_float4(g[j*4], g[j*4+1], g[j*4+2], g[j*4+3]);
            }
        }
    } else {
        // ================= CHAIN warp =================
        float Ap = 1.f, Bp = 0.f, Cp = 1.f, Dp = 0.f;   // A..D(t-1)
        float vi_c = g_proj[((size_t)b << 8) + 64 + i]; // v_0[i]
        float4 sc_c = g_scal[b];
        __syncthreads();   // prologue published (matches vector warp's bar)

        for (int t = 0; t < T_DIM; ++t) {
            // prefetch next-step scalars (consumed next iter — latency hidden)
            const int tn = (t + 1 < T_DIM) ? t + 1 : t;
            float  vi_n = g_proj[((size_t)(tn * B_DIM + b) << 8) + 64 + i];
            float4 sc_n = g_scal[tn * B_DIM + b];

            // combine raw dots (slot (t+1)&1, written at t-1) with A..D(t-1)
            const float* r = rd[(t + 1) & 1][rl];
            float p  = fmaf(Bp, r[5], Ap * r[0]);
            float rh = 0.5f * fmaf(Bp, r[6], Ap * r[1]);   // <s,m>/2
            float zz = fmaf(Bp, r[7], Ap * r[2]);
            float uh = 0.5f * fmaf(Dp, r[8], Cp * r[3]);   // <g,k>/2
            float wv = fmaf(Dp, r[9], Cp * r[4]);

            const float kk  = sc_c.x, mm = sc_c.y, kq = sc_c.w;
            const float kmh = 0.5f * sc_c.z;

            float A, Bc, Cc, Dc;
            rk4_chain<NS>(ns_rt, dt, h2, hd6, kk, mm, kmh, vi_c,
                          p, rh, uh, wv, A, Bc, Cc, Dc);

            // output: z = <s_end, q_t> = A*zz + B*kq
            float z = fmaf(Bc, kq, A * zz);
            if (cb == 0) {
                out[((size_t)t * B_DIM + b) * N_DIM + i] = z * z * sigmoidf(z);
                abcd[t & 1][rl] = make_float4(A, Bc, Cc, Dc);
            }
            Ap = A; Bp = Bc; Cp = Cc; Dp = Dc;
            vi_c = vi_n; sc_c = sc_n;
            __syncthreads();   // publish abcd[t&1] / rd[t&1]
        }
    }
}

__global__ void __launch_bounds__(64)
scan_kernel(const float* __restrict__ S0,
            const float* __restrict__ G0,
            const int*   __restrict__ ns_ptr,
            float* __restrict__ out) {
    __shared__ float  rd[2][8][12];
    __shared__ float4 abcd[2][8];

    const int ns = ns_ptr ? *ns_ptr : 4;
    if (ns == 4) {
        scan_impl<4>(S0, G0, out, 4, rd, abcd);
    } else {
        scan_impl<0>(S0, G0, out, ns, rd, abcd);
    }
}

// ---------------------------------------------------------------------------
extern "C" void kernel_launch(void* const* d_in, const int* in_sizes, int n_in,
                              void* d_out, int out_size) {
    const float* x  = (const float*)d_in[0];   // [T, B, 768]
    const float* S0 = (const float*)d_in[1];   // [B, 64, 64]
    const float* G0 = (const float*)d_in[2];   // [B, 64, 64]
    const float* W  = (const float*)d_in[3];   // [256, 768]
    const int*   ns = (n_in > 4) ? (const int*)d_in[4] : nullptr;
    float* out = (float*)d_out;

    dim3 ggrid(M_ROWS / 128, PROJ_C / 128);
    gemm_kernel<<<ggrid, 256>>>(x, W);

    norm_kernel<<<(M_ROWS * 32) / 256, 256>>>();

    // 256 blocks x 64 threads: per block, warp0 = vector, warp1 = chain
    scan_kernel<<<256, 64>>>(S0, G0, ns, out);
}

// round 17
// speedup vs baseline: 1.0606x; 1.0127x over previous
#include <cuda_runtime.h>
#include <cstdint>

// Problem dims (fixed by setup_inputs)
#define T_DIM 1024
#define B_DIM 32
#define D_DIM 768
#define N_DIM 64
#define PROJ_C 256          // 4*n : k | v | q | m
#define M_ROWS (T_DIM * B_DIM)

#define LOG2E 1.4426950408889634f

// Scratch: projection results [T, B, 256] fp32 (~33.5 MB) + per-row scalars
__device__ float  g_proj[(size_t)T_DIM * B_DIM * PROJ_C];
__device__ float4 g_scal[(size_t)T_DIM * B_DIM];    // {kk, mm, km, kq}
// Cross-step dots between row t-1 and row t (state-independent):
//   g_crossA = {<k',k>, <k',m>, <k',q>, <m',k>},  g_crossB = <m',m>   (' = t-1)
__device__ float4 g_crossA[(size_t)T_DIM * B_DIM];
__device__ float  g_crossB[(size_t)T_DIM * B_DIM];

// ---------------------------------------------------------------------------
__device__ __forceinline__ float ex2f(float x) {
    float y; asm("ex2.approx.ftz.f32 %0, %1;" : "=f"(y) : "f"(x)); return y;
}
__device__ __forceinline__ float rcpf(float x) {
    float y; asm("rcp.approx.ftz.f32 %0, %1;" : "=f"(y) : "f"(x)); return y;
}
__device__ __forceinline__ float tanhf_approx(float x) {
    float y; asm("tanh.approx.f32 %0, %1;" : "=f"(y) : "f"(x)); return y;
}
__device__ __forceinline__ float sigmoidf(float x) {   // high-precision (output path)
    return rcpf(1.0f + ex2f(-x * LOG2E));
}

// ---------------------------------------------------------------------------
// GEMM: proj[r, c] = sum_d x[r, d] * W[c, d]
// 128x128 tile, BK=16, 256 threads, 8x8 microtile, register-prefetch pipeline.
// (measured 309 us, fma=59% — parked)
// ---------------------------------------------------------------------------
__global__ void __launch_bounds__(256, 2)
gemm_kernel(const float* __restrict__ A, const float* __restrict__ W) {
    __shared__ float As[16][132];
    __shared__ float Bs[16][132];

    const int bm = blockIdx.x * 128;
    const int bn = blockIdx.y * 128;
    const int t  = threadIdx.x;
    const int tx = t & 15;
    const int ty = t >> 4;

    const int lrow = t >> 2;
    const int lkq  = (t & 3) * 4;

    float acc[8][8];
#pragma unroll
    for (int x = 0; x < 8; ++x)
#pragma unroll
        for (int y = 0; y < 8; ++y) acc[x][y] = 0.0f;

    float4 pa[2], pb[2];
#pragma unroll
    for (int p = 0; p < 2; ++p) {
        pa[p] = *(const float4*)(A + (size_t)(bm + p * 64 + lrow) * D_DIM + lkq);
        pb[p] = *(const float4*)(W + (size_t)(bn + p * 64 + lrow) * D_DIM + lkq);
    }

    for (int k0 = 0; k0 < D_DIM; k0 += 16) {
#pragma unroll
        for (int p = 0; p < 2; ++p) {
            int r = p * 64 + lrow;
            As[lkq + 0][r] = pa[p].x; As[lkq + 1][r] = pa[p].y;
            As[lkq + 2][r] = pa[p].z; As[lkq + 3][r] = pa[p].w;
            Bs[lkq + 0][r] = pb[p].x; Bs[lkq + 1][r] = pb[p].y;
            Bs[lkq + 2][r] = pb[p].z; Bs[lkq + 3][r] = pb[p].w;
        }
        __syncthreads();

        if (k0 + 16 < D_DIM) {
#pragma unroll
            for (int p = 0; p < 2; ++p) {
                pa[p] = *(const float4*)(A + (size_t)(bm + p * 64 + lrow) * D_DIM + k0 + 16 + lkq);
                pb[p] = *(const float4*)(W + (size_t)(bn + p * 64 + lrow) * D_DIM + k0 + 16 + lkq);
            }
        }

#pragma unroll
        for (int kk = 0; kk < 16; ++kk) {
            float4 a0 = *(const float4*)&As[kk][ty * 8];
            float4 a1 = *(const float4*)&As[kk][ty * 8 + 4];
            float4 b0 = *(const float4*)&Bs[kk][tx * 4];
            float4 b1 = *(const float4*)&Bs[kk][64 + tx * 4];
            float a[8]  = {a0.x, a0.y, a0.z, a0.w, a1.x, a1.y, a1.z, a1.w};
            float bb[8] = {b0.x, b0.y, b0.z, b0.w, b1.x, b1.y, b1.z, b1.w};
#pragma unroll
            for (int x = 0; x < 8; ++x)
#pragma unroll
                for (int y = 0; y < 8; ++y)
                    acc[x][y] = fmaf(a[x], bb[y], acc[x][y]);
        }
        __syncthreads();
    }

#pragma unroll
    for (int x = 0; x < 8; ++x) {
        float* dst = g_proj + (size_t)(bm + ty * 8 + x) * PROJ_C + bn;
        *(float4*)(dst + tx * 4)      = make_float4(acc[x][0], acc[x][1], acc[x][2], acc[x][3]);
        *(float4*)(dst + 64 + tx * 4) = make_float4(acc[x][4], acc[x][5], acc[x][6], acc[x][7]);
    }
}

// ---------------------------------------------------------------------------
// Normalize k (cols 0:64) and m (cols 192:256) per (t,b) row; also compute
// per-row scalars kk=<kn,kn>, mm=<mn,mn>, km=<kn,mn>, kq=<kn,q>.
// ---------------------------------------------------------------------------
__global__ void norm_kernel() {
    const int w    = (blockIdx.x * blockDim.x + threadIdx.x) >> 5;
    const int lane = threadIdx.x & 31;
    if (w >= M_ROWS) return;
    float* p = g_proj + (size_t)w * PROJ_C;

    float k0 = p[lane],       k1 = p[lane + 32];
    float q0 = p[128 + lane], q1 = p[160 + lane];
    float m0 = p[192 + lane], m1 = p[224 + lane];

    float sk  = fmaf(k0, k0, k1 * k1);
    float sm  = fmaf(m0, m0, m1 * m1);
    float skm = fmaf(k0, m0, k1 * m1);
    float skq = fmaf(k0, q0, k1 * q1);
#pragma unroll
    for (int o = 16; o > 0; o >>= 1) {
        float a = __shfl_xor_sync(0xffffffffu, sk,  o);
        float b = __shfl_xor_sync(0xffffffffu, sm,  o);
        float c = __shfl_xor_sync(0xffffffffu, skm, o);
        float d = __shfl_xor_sync(0xffffffffu, skq, o);
        sk += a; sm += b; skm += c; skq += d;
    }

    float ck = __fdividef(1.0f, sqrtf(sk) + 1e-6f);
    float cm = __fdividef(1.0f, sqrtf(sm) + 1e-6f);
    p[lane]       = k0 * ck;  p[lane + 32] = k1 * ck;
    p[192 + lane] = m0 * cm;  p[224 + lane] = m1 * cm;

    if (lane == 0) {
        float4 sc;
        sc.x = sk  * ck * ck;
        sc.y = sm  * cm * cm;
        sc.z = skm * ck * cm;
        sc.w = skq * ck;
        g_scal[w] = sc;
    }
}

// ---------------------------------------------------------------------------
// Cross-step dots: for each row w = t*B+b (t>=1), dots between normalized
// vectors of row w-B (t-1) and row w (t). One warp per row. t=0 -> zeros
// (consumed with Bp=Dp=0 at chain step 0, value irrelevant).
// Must run AFTER norm_kernel.
// ---------------------------------------------------------------------------
__global__ void cross_kernel() {
    const int w    = (blockIdx.x * blockDim.x + threadIdx.x) >> 5;
    const int lane = threadIdx.x & 31;
    if (w >= M_ROWS) return;

    if (w < B_DIM) {   // t == 0
        if (lane == 0) {
            g_crossA[w] = make_float4(0.f, 0.f, 0.f, 0.f);
            g_crossB[w] = 0.f;
        }
        return;
    }

    const float* cur = g_proj + (size_t)w * PROJ_C;
    const float* prv = cur - (size_t)B_DIM * PROJ_C;

    float k0  = cur[lane],       k1  = cur[lane + 32];
    float q0  = cur[128 + lane], q1  = cur[160 + lane];
    float m0  = cur[192 + lane], m1  = cur[224 + lane];
    float kp0 = prv[lane],       kp1 = prv[lane + 32];
    float mp0 = prv[192 + lane], mp1 = prv[224 + lane];

    float dkk = fmaf(kp0, k0, kp1 * k1);
    float dkm = fmaf(kp0, m0, kp1 * m1);
    float dkq = fmaf(kp0, q0, kp1 * q1);
    float dmk = fmaf(mp0, k0, mp1 * k1);
    float dmm = fmaf(mp0, m0, mp1 * m1);
#pragma unroll
    for (int o = 16; o > 0; o >>= 1) {
        dkk += __shfl_xor_sync(0xffffffffu, dkk, o);
        dkm += __shfl_xor_sync(0xffffffffu, dkm, o);
        dkq += __shfl_xor_sync(0xffffffffu, dkq, o);
        dmk += __shfl_xor_sync(0xffffffffu, dmk, o);
        dmm += __shfl_xor_sync(0xffffffffu, dmm, o);
    }

    if (lane == 0) {
        g_crossA[w] = make_float4(dkk, dkm, dkq, dmk);
        g_crossB[w] = dmm;
    }
}

// ---------------------------------------------------------------------------
// Scalar-space RK4 chain, tanh-gate form (verified rel_err 2.4e-7 in R12).
// ---------------------------------------------------------------------------
template<int NS>
__device__ __forceinline__ void rk4_chain(
    int ns_rt, float dt, float h2, float hd6,
    float kk, float mm, float kmh, float vi,
    float p, float rh, float uh, float wv,
    float& A, float& Bc, float& Cc, float& Dc)
{
    A = 1.f; Bc = 0.f; Cc = 1.f; Dc = 0.f;
    float pc = p, rc = rh, uc = uh, wc = wv;
    const int n = (NS > 0) ? NS : ns_rt;
#pragma unroll
    for (int ssi = 0; ssi < n; ++ssi) {
        // hoisted per-substep constants (off critical path)
        const float h2pc = h2 * pc,  dtpc = dt * pc;
        const float h2rc = h2 * rc,  dtrc = dt * rc;
        const float h2uc = h2 * uc,  dtuc = dt * uc;
        const float h2wc = h2 * wc,  dtwc = dt * wc;
        const float h2kk = h2 * kk,  dtkk = dt * kk;
        const float h2km = h2 * kmh, dtkm = dt * kmh;
        const float h2mm = h2 * mm,  dtmm = dt * mm;

        float aSa = 0.f, aSb = 0.f, aGc = 0.f, aGd = 0.f;
        float dSa = 0.f, dSb = 0.f, dGc = 0.f, dGd = 0.f;  // prev-stage derivs
#pragma unroll
        for (int st = 0; st < 4; ++st) {
            float as, bs, cc, dc, p_st, rh_st, uh_st, w_st;
            if (st == 0) {
                as = 1.f; bs = 0.f; cc = 1.f; dc = 0.f;
                p_st = pc; rh_st = rc; uh_st = uc; w_st = wc;
            } else {
                const bool last = (st == 3);
                const float cst  = last ? dt : h2;
                const float cpc  = last ? dtpc : h2pc;
                const float crc  = last ? dtrc : h2rc;
                const float cuc  = last ? dtuc : h2uc;
                const float cwc  = last ? dtwc : h2wc;
                const float ckk  = last ? dtkk : h2kk;
                const float ckm  = last ? dtkm : h2km;
                const float cmm  = last ? dtmm : h2mm;
                as = fmaf(cst, dSa, 1.f);  bs = cst * dSb;
                cc = fmaf(cst, dGc, 1.f);  dc = cst * dGd;
                p_st  = fmaf(dSb, ckk, fmaf(dSa, cpc, pc));
                rh_st = fmaf(dSb, ckm, fmaf(dSa, crc, rc));
                uh_st = fmaf(dGd, ckm, fmaf(dGc, cuc, uc));
                w_st  = fmaf(dGd, cmm, fmaf(dGc, cwc, wc));
            }
            // gates via tanh: an = 1 - sigmoid(u) = 0.5 - 0.5*tanh(u/2)
            float Tu = tanhf_approx(uh_st);
            float Tr = tanhf_approx(rh_st);
            float dSs = vi - p_st;
            float dGs = dSs - w_st;
            float has = 0.5f * as, hbs = 0.5f * bs;
            float hcc = 0.5f * cc, hdc = 0.5f * dc;
            dSa = fmaf(Tu, has, -has);          // -an*as
            dSb = fmaf(Tu, hbs, dSs - hbs);     // dSs - an*bs
            dGc = fmaf(Tr, hcc, -hcc);
            dGd = fmaf(Tr, hdc, dGs - hdc);
            float wgt = (st == 1 || st == 2) ? 2.0f : 1.0f;
            aSa = fmaf(wgt, dSa, aSa);
            aSb = fmaf(wgt, dSb, aSb);
            aGc = fmaf(wgt, dGc, aGc);
            aGd = fmaf(wgt, dGd, aGd);
        }
        float a_s = fmaf(hd6, aSa, 1.0f), b_s = hd6 * aSb;
        float c_g = fmaf(hd6, aGc, 1.0f), d_g = hd6 * aGd;
        A  = a_s * A;  Bc = fmaf(a_s, Bc, b_s);
        Cc = c_g * Cc; Dc = fmaf(c_g, Dc, d_g);
        pc = fmaf(b_s, kk,  a_s * pc);
        rc = fmaf(b_s, kmh, a_s * rc);
        uc = fmaf(d_g, kmh, c_g * uc);
        wc = fmaf(d_g, mm,  c_g * wc);
    }
}

// ---------------------------------------------------------------------------
// Warp-specialized scan (R12 structure). Cross-step dots are now PRECOMPUTED
// (cross_kernel) — vector warp computes only the 5 state dots; chain warp
// prefetches the cross dots into registers (no smem hop for them).
// Block = 2 warps, 8 rows. One __syncthreads per timestep; double-buffered
// rd/abcd: read slot (t+1)&1, write slot t&1.
// ---------------------------------------------------------------------------
template<int NS>
__device__ __forceinline__ void scan_impl(
    const float* __restrict__ S0, const float* __restrict__ G0,
    float* __restrict__ out, int ns_rt,
    float rd[2][8][8], float4 abcd[2][8])
{
    const int b    = (int)blockIdx.x >> 3;
    const int rg   = (int)blockIdx.x & 7;
    const int wid  = threadIdx.x >> 5;        // 0 = vector, 1 = chain
    const int lane = threadIdx.x & 31;
    const int rl   = lane >> 2;               // row in group (0..7)
    const int cb   = lane & 3;                // column block (0..3)
    const int i    = rg * 8 + rl;             // global row 0..63
    const int cofs = cb * 16;

    const float dt  = __fdividef(1.0f, (float)((NS > 0) ? NS : ns_rt));
    const float h2  = 0.5f * dt;
    const float hd6 = dt * (1.0f / 6.0f);

    const size_t sbase = ((size_t)b * N_DIM + i) * N_DIM + cofs;

    if (wid == 0) {
        // ================= VECTOR warp =================
        float s[16], g[16], kc[16], mc[16], kn[16], mn[16], qn[16];
#pragma unroll
        for (int j = 0; j < 4; ++j) {
            float4 a = *(const float4*)(S0 + sbase + j * 4);
            s[j*4+0]=a.x; s[j*4+1]=a.y; s[j*4+2]=a.z; s[j*4+3]=a.w;
            float4 c = *(const float4*)(G0 + sbase + j * 4);
            g[j*4+0]=c.x; g[j*4+1]=c.y; g[j*4+2]=c.z; g[j*4+3]=c.w;
        }
        {   // t = 0 vectors into the "next" slots
            const float* pp = g_proj + ((size_t)b << 8);
#pragma unroll
            for (int j = 0; j < 4; ++j) {
                float4 a = *(const float4*)(pp + cofs + j * 4);
                kn[j*4+0]=a.x; kn[j*4+1]=a.y; kn[j*4+2]=a.z; kn[j*4+3]=a.w;
                float4 c = *(const float4*)(pp + 192 + cofs + j * 4);
                mn[j*4+0]=c.x; mn[j*4+1]=c.y; mn[j*4+2]=c.z; mn[j*4+3]=c.w;
                float4 d = *(const float4*)(pp + 128 + cofs + j * 4);
                qn[j*4+0]=d.x; qn[j*4+1]=d.y; qn[j*4+2]=d.z; qn[j*4+3]=d.w;
            }
#pragma unroll
            for (int j = 0; j < 16; ++j) { kc[j] = kn[j]; mc[j] = mn[j]; }
        }
        // Prologue: dots of initial state with t=0 vectors -> rd[1];
        // abcd[1] = identity so iter-0 update is a no-op.
        {
            float d0=0.f,d1=0.f,d2=0.f,d3=0.f,d4=0.f;
#pragma unroll
            for (int j = 0; j < 16; ++j) {
                d0 = fmaf(s[j], kn[j], d0);
                d1 = fmaf(s[j], mn[j], d1);
                d2 = fmaf(s[j], qn[j], d2);
                d3 = fmaf(g[j], kn[j], d3);
                d4 = fmaf(g[j], mn[j], d4);
            }
#pragma unroll
            for (int o = 1; o <= 2; o <<= 1) {
                d0 += __shfl_xor_sync(0xffffffffu, d0, o);
                d1 += __shfl_xor_sync(0xffffffffu, d1, o);
                d2 += __shfl_xor_sync(0xffffffffu, d2, o);
                d3 += __shfl_xor_sync(0xffffffffu, d3, o);
                d4 += __shfl_xor_sync(0xffffffffu, d4, o);
            }
            if (cb == 0) {
                float* r = rd[1][rl];
                r[0]=d0; r[1]=d1; r[2]=d2; r[3]=d3; r[4]=d4;
                abcd[1][rl] = make_float4(1.f, 0.f, 1.f, 0.f);
            }
        }
        __syncthreads();   // prologue published

        for (int t = 0; t < T_DIM; ++t) {
            // update with A..D(t-1) from slot (t+1)&1
            float4 ab = abcd[(t + 1) & 1][rl];
#pragma unroll
            for (int j = 0; j < 16; ++j) {
                s[j] = fmaf(ab.x, s[j], ab.y * kc[j]);
                g[j] = fmaf(ab.z, g[j], ab.w * mc[j]);
                kc[j] = kn[j];
                mc[j] = mn[j];
            }
            // prefetch t+1 vectors
            {
                const int tn = (t + 1 < T_DIM) ? t + 1 : t;
                const float* np = g_proj + ((size_t)(tn * B_DIM + b) << 8);
#pragma unroll
                for (int j = 0; j < 4; ++j) {
                    float4 a = *(const float4*)(np + cofs + j * 4);
                    kn[j*4+0]=a.x; kn[j*4+1]=a.y; kn[j*4+2]=a.z; kn[j*4+3]=a.w;
                    float4 c = *(const float4*)(np + 192 + cofs + j * 4);
                    mn[j*4+0]=c.x; mn[j*4+1]=c.y; mn[j*4+2]=c.z; mn[j*4+3]=c.w;
                    float4 d = *(const float4*)(np + 128 + cofs + j * 4);
                    qn[j*4+0]=d.x; qn[j*4+1]=d.y; qn[j*4+2]=d.z; qn[j*4+3]=d.w;
                }
            }
            // 5 state dots: {s,g} x {kn,mn,qn}  (cross dots precomputed)
            float skp=0.f, smp=0.f, sqp=0.f, gkp=0.f, gmp=0.f;
#pragma unroll
            for (int j = 0; j < 16; ++j) {
                skp = fmaf(s[j], kn[j], skp);
                smp = fmaf(s[j], mn[j], smp);
                sqp = fmaf(s[j], qn[j], sqp);
                gkp = fmaf(g[j], kn[j], gkp);
                gmp = fmaf(g[j], mn[j], gmp);
            }
#pragma unroll
            for (int o = 1; o <= 2; o <<= 1) {
                skp += __shfl_xor_sync(0xffffffffu, skp, o);
                smp += __shfl_xor_sync(0xffffffffu, smp, o);
                sqp += __shfl_xor_sync(0xffffffffu, sqp, o);
                gkp += __shfl_xor_sync(0xffffffffu, gkp, o);
                gmp += __shfl_xor_sync(0xffffffffu, gmp, o);
            }
            if (cb == 0) {
                float* r = rd[t & 1][rl];
                r[0]=skp; r[1]=smp; r[2]=sqp; r[3]=gkp; r[4]=gmp;
            }
            __syncthreads();   // publish rd[t&1] / abcd[t&1]
        }

        // Final update with A..D(T-1) and state writeback
        {
            float4 ab = abcd[(T_DIM - 1) & 1][rl];
#pragma unroll
            for (int j = 0; j < 16; ++j) {
                s[j] = fmaf(ab.x, s[j], ab.y * kc[j]);
                g[j] = fmaf(ab.z, g[j], ab.w * mc[j]);
            }
            float* Sout = out + (size_t)T_DIM * B_DIM * N_DIM;
            float* Gout = Sout + (size_t)B_DIM * N_DIM * N_DIM;
#pragma unroll
            for (int j = 0; j < 4; ++j) {
                *(float4*)(Sout + sbase + j * 4) =
                    make_float4(s[j*4], s[j*4+1], s[j*4+2], s[j*4+3]);
                *(float4*)(Gout + sbase + j * 4) =
                    make_float4(g[j*4], g[j*4+1], g[j*4+2], g[j*4+3]);
            }
        }
    } else {
        // ================= CHAIN warp =================
        float Ap = 1.f, Bp = 0.f, Cp = 1.f, Dp = 0.f;   // A..D(t-1)
        float vi_c = g_proj[((size_t)b << 8) + 64 + i]; // v_0[i]
        float4 sc_c = g_scal[b];
        float4 cxA  = g_crossA[b];                       // cross(pair -1->0): zeros
        float  cxB  = g_crossB[b];
        __syncthreads();   // prologue published (matches vector warp's bar)

        for (int t = 0; t < T_DIM; ++t) {
            // prefetch next-step scalars + cross dots (consumed next iter)
            const int tn = (t + 1 < T_DIM) ? t + 1 : t;
            float  vi_n = g_proj[((size_t)(tn * B_DIM + b) << 8) + 64 + i];
            float4 sc_n = g_scal[tn * B_DIM + b];
            float4 cxA_n = g_crossA[tn * B_DIM + b];
            float  cxB_n = g_crossB[tn * B_DIM + b];

            // combine state dots (slot (t+1)&1, written at t-1) with A..D(t-1)
            // and precomputed cross dots (registers)
            const float* r = rd[(t + 1) & 1][rl];
            float p  = fmaf(Bp, cxA.x, Ap * r[0]);
            float rh = 0.5f * fmaf(Bp, cxA.y, Ap * r[1]);   // <s,m>/2
            float zz = fmaf(Bp, cxA.z, Ap * r[2]);
            float uh = 0.5f * fmaf(Dp, cxA.w, Cp * r[3]);   // <g,k>/2
            float wv = fmaf(Dp, cxB,  Cp * r[4]);

            const float kk  = sc_c.x, mm = sc_c.y, kq = sc_c.w;
            const float kmh = 0.5f * sc_c.z;

            float A, Bc, Cc, Dc;
            rk4_chain<NS>(ns_rt, dt, h2, hd6, kk, mm, kmh, vi_c,
                          p, rh, uh, wv, A, Bc, Cc, Dc);

            // output: z = <s_end, q_t> = A*zz + B*kq
            float z = fmaf(Bc, kq, A * zz);
            if (cb == 0) {
                out[((size_t)t * B_DIM + b) * N_DIM + i] = z * z * sigmoidf(z);
                abcd[t & 1][rl] = make_float4(A, Bc, Cc, Dc);
            }
            Ap = A; Bp = Bc; Cp = Cc; Dp = Dc;
            vi_c = vi_n; sc_c = sc_n; cxA = cxA_n; cxB = cxB_n;
            __syncthreads();   // publish abcd[t&1] / rd[t&1]
        }
    }
}

__global__ void __launch_bounds__(64)
scan_kernel(const float* __restrict__ S0,
            const float* __restrict__ G0,
            const int*   __restrict__ ns_ptr,
            float* __restrict__ out) {
    __shared__ float  rd[2][8][8];
    __shared__ float4 abcd[2][8];

    const int ns = ns_ptr ? *ns_ptr : 4;
    if (ns == 4) {
        scan_impl<4>(S0, G0, out, 4, rd, abcd);
    } else {
        scan_impl<0>(S0, G0, out, ns, rd, abcd);
    }
}

// ---------------------------------------------------------------------------
extern "C" void kernel_launch(void* const* d_in, const int* in_sizes, int n_in,
                              void* d_out, int out_size) {
    const float* x  = (const float*)d_in[0];   // [T, B, 768]
    const float* S0 = (const float*)d_in[1];   // [B, 64, 64]
    const float* G0 = (const float*)d_in[2];   // [B, 64, 64]
    const float* W  = (const float*)d_in[3];   // [256, 768]
    const int*   ns = (n_in > 4) ? (const int*)d_in[4] : nullptr;
    float* out = (float*)d_out;

    dim3 ggrid(M_ROWS / 128, PROJ_C / 128);
    gemm_kernel<<<ggrid, 256>>>(x, W);

    norm_kernel<<<(M_ROWS * 32) / 256, 256>>>();
    cross_kernel<<<(M_ROWS * 32) / 256, 256>>>();

    // 256 blocks x 64 threads: per block, warp0 = vector, warp1 = chain
    scan_kernel<<<256, 64>>>(S0, G0, ns, out);
}